// round 7
// baseline (speedup 1.0000x reference)
#include <cuda_runtime.h>
#include <cuda_bf16.h>

#define HLR 128
#define WLR 128
#define HH 512
#define WH 512
#define CC 64
#define NPIX (HH*WH)      // 262144
#define NPIX2 (514*512)   // padded plane: 1 zero row above + below
#define NQ 262144

typedef unsigned long long ull;

// ---- packed f32x2 helpers (sm_103a: fma.rn.f32x2 -> FFMA2) ----
__device__ __forceinline__ ull pk2(float lo, float hi) {
    ull r; asm("mov.b64 %0, {%1, %2};" : "=l"(r) : "f"(lo), "f"(hi)); return r;
}
__device__ __forceinline__ void upk2(ull v, float& lo, float& hi) {
    asm("mov.b64 {%0, %1}, %2;" : "=f"(lo), "=f"(hi) : "l"(v));
}
__device__ __forceinline__ ull fma2(ull a, ull b, ull c) {
    ull d; asm("fma.rn.f32x2 %0, %1, %2, %3;" : "=l"(d) : "l"(a), "l"(b), "l"(c)); return d;
}
__device__ __forceinline__ ull mul2(ull a, ull b) {
    ull d; asm("mul.rn.f32x2 %0, %1, %2;" : "=l"(d) : "l"(a), "l"(b)); return d;
}

// ---- scratch (device globals: allocation-free) ----
__device__ __align__(16) ull g_feat2[32*HLR*WLR];            // 4 MB [c2][pix]
// g_hidden2: channel-pair planes, PHASE-PERMUTED pixels, PADDED rows:
// [c2][(y+1)*512 + w*128 + g], x = 4*g + w; rows 0 and 513 are zero.
__device__ __align__(16) ull g_hidden2[32*NPIX2];            // ~67 MB
// g_pred4: PHASE-PERMUTED [y*512 + w*128 + g] {o0,o1,o2,-}
__device__ __align__(16) float4 g_pred4[NPIX];               // 4 MB
__device__ float g_off[16*2];
__device__ float g_r[16*4];
__device__ __align__(16) float g_A[16*512];      // [ph][c*8+k]
__device__ __align__(16) float g_B[16*512];      // [ph][k*64+c]

// ============ Kernel 1: encoder conv3x3 (blocks 0..511) + phase MLP (block 512) ============
__global__ void __launch_bounds__(256)
k_enc_phase(const float* __restrict__ inp,
            const float* __restrict__ ew, const float* __restrict__ eb,
            const float* __restrict__ w1, const float* __restrict__ b1,
            const float* __restrict__ w2, const float* __restrict__ b2,
            const float* __restrict__ rw, const float* __restrict__ rb,
            const float* __restrict__ ow, const float* __restrict__ ob) {
    __shared__ float sw[27*64];
    __shared__ float sb[64];
    __shared__ float sw2[64*65];
    __shared__ float se1[1024];
    __shared__ float se2[1024];
    int t = threadIdx.x;

    if (blockIdx.x < 512) {
        for (int idx = t; idx < 27*64; idx += 256) {
            int j = idx >> 6, c = idx & 63;
            sw[idx] = __ldg(&ew[c*27 + j]);
        }
        if (t < 64) sb[t] = __ldg(&eb[t]);
        __syncthreads();

        int px = blockIdx.x*32 + (t & 31);
        int grp = t >> 5;
        int x = px & 127, y = px >> 7;

        float in[27];
        #pragma unroll
        for (int ci = 0; ci < 3; ci++)
            #pragma unroll
            for (int ky = 0; ky < 3; ky++) {
                int yy = y + ky - 1;
                bool ry = ((unsigned)yy < 128u);
                #pragma unroll
                for (int kx = 0; kx < 3; kx++) {
                    int xx = x + kx - 1;
                    in[ci*9 + ky*3 + kx] = (ry && ((unsigned)xx < 128u))
                        ? __ldg(&inp[(ci*128 + yy)*128 + xx]) : 0.0f;
                }
            }
        #pragma unroll
        for (int u = 0; u < 2; u++) {
            int c4 = grp*2 + u;
            float4 acc = make_float4(sb[c4*4+0], sb[c4*4+1], sb[c4*4+2], sb[c4*4+3]);
            #pragma unroll
            for (int j = 0; j < 27; j++) {
                float fin = in[j];
                const float4 wv = *(const float4*)&sw[j*64 + c4*4];
                acc.x = fmaf(fin, wv.x, acc.x);
                acc.y = fmaf(fin, wv.y, acc.y);
                acc.z = fmaf(fin, wv.z, acc.z);
                acc.w = fmaf(fin, wv.w, acc.w);
            }
            g_feat2[(c4*2+0)*16384 + px] = pk2(acc.x, acc.y);
            g_feat2[(c4*2+1)*16384 + px] = pk2(acc.z, acc.w);
        }
    } else {
        for (int idx = t; idx < 4096; idx += 256) {
            int c = idx >> 6, j = idx & 63;
            sw2[c*65 + j] = __ldg(&w2[idx]);
        }
        #pragma unroll
        for (int it = 0; it < 4; it++) {
            int item = t + it*256;
            int ph = item >> 6, c = item & 63;
            int py = ph >> 2, px = ph & 3;
            float ch = (py + 0.5f)/4.0f; ch = ch - floorf(ch + 0.001f) - 0.5f;
            float cw = (px + 0.5f)/4.0f; cw = cw - floorf(cw + 0.001f) - 0.5f;
            const float cs = 0.25f;
            float s = __ldg(&b1[c]);
            s = fmaf(__ldg(&w1[c*4+0]), cs, s);
            s = fmaf(__ldg(&w1[c*4+1]), cs, s);
            s = fmaf(__ldg(&w1[c*4+2]), ch, s);
            s = fmaf(__ldg(&w1[c*4+3]), cw, s);
            se1[item] = fmaxf(s, 0.0f);
        }
        __syncthreads();
        #pragma unroll
        for (int it = 0; it < 4; it++) {
            int item = t + it*256;
            int ph = item >> 6, c = item & 63;
            float s = __ldg(&b2[c]);
            #pragma unroll 8
            for (int j = 0; j < 64; j++)
                s = fmaf(sw2[c*65 + j], se1[ph*64 + j], s);
            se2[item] = fmaxf(s, 0.0f);
        }
        __syncthreads();
        if (t < 96) {
            int ph = t / 6, which = t % 6;
            if (which < 2) {
                float s = __ldg(&ob[which]);
                for (int j = 0; j < 64; j++)
                    s = fmaf(__ldg(&ow[which*64 + j]), se2[ph*64 + j], s);
                g_off[ph*2 + which] = s;
            } else {
                int e = which - 2;
                float s = __ldg(&rb[e]);
                for (int j = 0; j < 64; j++)
                    s = fmaf(__ldg(&rw[e*64 + j]), se2[ph*64 + j], s);
                g_r[ph*4 + e] = 1.0f/(1.0f + expf(-s));
            }
        }
    }
}

// ============ Kernel 2a: zero hidden pad rows (rows 0 and 513 of each plane) ============
__global__ void zero_pad() {
    int t = blockIdx.x*blockDim.x + threadIdx.x;   // 32768 items
    int c2 = t >> 10;
    int r  = (t >> 9) & 1;                          // 0 -> row 0, 1 -> row 513
    int i  = t & 511;
    g_hidden2[c2*NPIX2 + (r ? 513*512 : 0) + i] = 0ULL;
}

// ============ Kernel 2b: build A(r), B(r) per phase ============
__global__ void build_ab(const float* __restrict__ wc, const float* __restrict__ we) {
    int t = blockIdx.x*blockDim.x + threadIdx.x;
    if (t < 8192) {
        int ph = t >> 9, rem = t & 511;
        int c = rem >> 3, k = rem & 7;
        float s = 0.0f;
        #pragma unroll
        for (int e = 0; e < 4; e++)
            s = fmaf(g_r[ph*4+e], __ldg(&we[(e*64 + c)*8 + k]), s);
        g_A[ph*512 + c*8 + k] = s;
    } else {
        int u = t - 8192;
        int ph = u >> 9, rem = u & 511;
        int k = rem >> 6, c = rem & 63;
        float s = 0.0f;
        #pragma unroll
        for (int e = 0; e < 4; e++)
            s = fmaf(g_r[ph*4+e], __ldg(&wc[(e*8 + k)*64 + c]), s);
        g_B[ph*512 + k*64 + c] = s;
    }
}

// ============ Kernel 3: fused grid-sample + expert mixing (2-pass, low-reg) ============
__global__ void __launch_bounds__(128)
main_fused() {
    __shared__ ull sBt[4*264];
    __shared__ ull sAt[4*264];

    int tid = threadIdx.x;
    int p0 = blockIdx.x << 7;
    int y  = p0 >> 9;
    int X0 = p0 & 511;
    int py4 = y & 3;

    const ull* GB = (const ull*)g_B;
    for (int i = tid; i < 1024; i += 128) {
        int phl = i >> 8, ii = i & 255;
        int c2 = ii >> 3, k = ii & 7;
        int ph = py4*4 + phl;
        sBt[phl*264 + ii] = GB[ph*256 + k*32 + c2];
        sAt[phl*264 + ii] = pk2(g_A[ph*512 + (2*c2)*8 + k],
                                g_A[ph*512 + (2*c2+1)*8 + k]);
    }
    __syncthreads();

    int w    = tid >> 5;
    int lane = tid & 31;
    int x = X0 + 4*lane + w;
    int ph = py4*4 + w;

    float off0 = g_off[ph*2+0];
    float off1 = g_off[ph*2+1];

    float xs = ((float)x + 0.5f)*0.25f - 0.5f + off0;
    float ys = ((float)y + 0.5f)*0.25f - 0.5f + off1;
    float x0f = floorf(xs), y0f = floorf(ys);
    float wx1 = xs - x0f, wx0 = 1.0f - wx1;
    float wy1 = ys - y0f, wy0 = 1.0f - wy1;
    int x0 = (int)x0f, y0 = (int)y0f;
    int x1 = x0 + 1, y1 = y0 + 1;
    float mx0 = ((unsigned)x0 < 128u) ? 1.0f : 0.0f;
    float mx1 = ((unsigned)x1 < 128u) ? 1.0f : 0.0f;
    float my0 = ((unsigned)y0 < 128u) ? 1.0f : 0.0f;
    float my1 = ((unsigned)y1 < 128u) ? 1.0f : 0.0f;
    float w00 = wy0*wx0*my0*mx0;
    float w01 = wy0*wx1*my0*mx1;
    float w10 = wy1*wx0*my1*mx0;
    float w11 = wy1*wx1*my1*mx1;
    int xc0 = min(max(x0,0),127), xc1 = min(max(x1,0),127);
    int yc0 = min(max(y0,0),127), yc1 = min(max(y1,0),127);
    int i00 = yc0*128 + xc0, i01 = yc0*128 + xc1;
    int i10 = yc1*128 + xc0, i11 = yc1*128 + xc1;

    ull W00 = pk2(w00,w00), W01 = pk2(w01,w01);
    ull W10 = pk2(w10,w10), W11 = pk2(w11,w11);

    // ---- pass A: accumulate mid = B * fea0 ----
    ull acc[8] = {0,0,0,0,0,0,0,0};
    const ull* Bp = sBt + w*264;
    #pragma unroll
    for (int c2 = 0; c2 < 32; c2++) {
        const ull* fp = g_feat2 + c2*16384;
        ull f = fma2(__ldg(fp+i11), W11,
                fma2(__ldg(fp+i10), W10,
                fma2(__ldg(fp+i01), W01,
                mul2(__ldg(fp+i00), W00))));
        #pragma unroll
        for (int k = 0; k < 8; k++)
            acc[k] = fma2(Bp[c2*8 + k], f, acc[k]);
    }
    ull mdup[8];
    #pragma unroll
    for (int k = 0; k < 8; k++) {
        float lo, hi; upk2(acc[k], lo, hi);
        float s = lo + hi;
        mdup[k] = pk2(s, s);
    }

    // ---- pass B: hidden = fea0 + A*mid, store permuted+padded ----
    int g = (X0 >> 2) + lane;
    ull* H = g_hidden2 + (((y+1) << 9) + (w << 7) + g);
    const ull* Ap = sAt + w*264;
    #pragma unroll
    for (int c2 = 31; c2 >= 0; c2--) {
        const ull* fp = g_feat2 + c2*16384;
        ull h = fma2(__ldg(fp+i11), W11,
                fma2(__ldg(fp+i10), W10,
                fma2(__ldg(fp+i01), W01,
                mul2(__ldg(fp+i00), W00))));
        #pragma unroll
        for (int k = 0; k < 8; k++)
            h = fma2(Ap[c2*8 + k], mdup[k], h);
        H[c2*NPIX2] = h;
    }
}

// ============ Kernel 4: tail conv3x3 (64 -> 3), streaming, pad rows, 2 rows/thread ============
// Thread = one x-column, 2 output rows. 1024 blocks x 128 threads.
// Pad rows make all y-loads unconditional: immediate offsets off 3 plane pointers.
__global__ void __launch_bounds__(128)
tail_conv(const float* __restrict__ tw, const float* __restrict__ tb) {
    __shared__ ull sw2[864];   // [c2][o][ky*3+kx] broadcast pairs

    for (int idx = threadIdx.x; idx < 864; idx += 128) {
        int c2 = idx / 27, rem = idx % 27;
        int o = rem / 9, t9 = rem % 9;
        sw2[idx] = pk2(__ldg(&tw[(o*64 + 2*c2)*9 + t9]),
                       __ldg(&tw[(o*64 + 2*c2+1)*9 + t9]));
    }
    __syncthreads();

    int w    = threadIdx.x >> 5;
    int lane = threadIdx.x & 31;
    int Y0 = (blockIdx.x >> 2) << 1;               // 256 row-pairs
    int g  = ((blockIdx.x & 3) << 5) + lane;       // 4 g-quarters

    int oC = (w << 7) + g;
    int oL, oR;
    bool vl = true, vr = true;
    if (w > 0) { oL = ((w-1) << 7) + g; }
    else       { oL = (3 << 7) + g - 1; vl = (g > 0); }
    if (w < 3) { oR = ((w+1) << 7) + g; }
    else       { oR = g + 1; vr = (g < 127); }

    // padded row of y=Y0-1 is Y0; base pointers at that row
    const ull* pL = g_hidden2 + (ull)Y0*512 + oL;
    const ull* pC = g_hidden2 + (ull)Y0*512 + oC;
    const ull* pR = g_hidden2 + (ull)Y0*512 + oR;

    ull a0[3] = {0,0,0}, a1[3] = {0,0,0};

    #pragma unroll 4
    for (int c2 = 0; c2 < 32; c2++) {
        ull vL0 = vl ? __ldg(pL)        : 0ULL;
        ull vL1 = vl ? __ldg(pL + 512)  : 0ULL;
        ull vL2 = vl ? __ldg(pL + 1024) : 0ULL;
        ull vL3 = vl ? __ldg(pL + 1536) : 0ULL;
        ull vC0 = __ldg(pC);
        ull vC1 = __ldg(pC + 512);
        ull vC2 = __ldg(pC + 1024);
        ull vC3 = __ldg(pC + 1536);
        ull vR0 = vr ? __ldg(pR)        : 0ULL;
        ull vR1 = vr ? __ldg(pR + 512)  : 0ULL;
        ull vR2 = vr ? __ldg(pR + 1024) : 0ULL;
        ull vR3 = vr ? __ldg(pR + 1536) : 0ULL;
        pL += NPIX2; pC += NPIX2; pR += NPIX2;

        const ull* wp = &sw2[c2*27];
        #pragma unroll
        for (int o = 0; o < 3; o++) {
            ull w00 = wp[o*9+0], w01 = wp[o*9+1], w02 = wp[o*9+2];
            ull w10 = wp[o*9+3], w11 = wp[o*9+4], w12 = wp[o*9+5];
            ull w20 = wp[o*9+6], w21 = wp[o*9+7], w22 = wp[o*9+8];
            a0[o] = fma2(vL0,w00, fma2(vC0,w01, fma2(vR0,w02,
                    fma2(vL1,w10, fma2(vC1,w11, fma2(vR1,w12,
                    fma2(vL2,w20, fma2(vC2,w21, fma2(vR2,w22, a0[o])))))))));
            a1[o] = fma2(vL1,w00, fma2(vC1,w01, fma2(vR1,w02,
                    fma2(vL2,w10, fma2(vC2,w11, fma2(vR2,w12,
                    fma2(vL3,w20, fma2(vC3,w21, fma2(vR3,w22, a1[o])))))))));
        }
    }

    float b0 = __ldg(&tb[0]), b1 = __ldg(&tb[1]), b2 = __ldg(&tb[2]);
    {
        float l0,h0,l1,h1,l2,h2;
        upk2(a0[0], l0, h0); upk2(a0[1], l1, h1); upk2(a0[2], l2, h2);
        g_pred4[(Y0 << 9) + oC] = make_float4(b0+l0+h0, b1+l1+h1, b2+l2+h2, 0.0f);
        upk2(a1[0], l0, h0); upk2(a1[1], l1, h1); upk2(a1[2], l2, h2);
        g_pred4[((Y0+1) << 9) + oC] = make_float4(b0+l0+h0, b1+l1+h1, b2+l2+h2, 0.0f);
    }
}

// ============ Kernel 5: query gather (nearest, round-half-even) ============
__global__ void gather_q(const float* __restrict__ coord,
                         const float* __restrict__ cell,
                         float* __restrict__ out) {
    int q = blockIdx.x*blockDim.x + threadIdx.x;
    if (q >= NQ) return;
    float cy = __ldg(&coord[q*2+0]);
    float cx = __ldg(&coord[q*2+1]);
    float ly = __ldg(&cell[q*2+0]);
    float lx = __ldg(&cell[q*2+1]);
    float gyq = fminf(fmaxf(cy - ly*0.5f + 1e-6f, -1.0f + 1e-6f), 1.0f - 1e-6f);
    float gxq = fminf(fmaxf(cx - lx*0.5f + 1e-6f, -1.0f + 1e-6f), 1.0f - 1e-6f);
    int xi = (int)rintf((gxq + 1.0f)*0.5f*511.0f);
    int yi = (int)rintf((gyq + 1.0f)*0.5f*511.0f);
    xi = min(max(xi,0),511);
    yi = min(max(yi,0),511);
    int idx = (yi << 9) + ((xi & 3) << 7) + (xi >> 2);
    float4 v = __ldg(&g_pred4[idx]);
    out[q*3+0] = v.x;
    out[q*3+1] = v.y;
    out[q*3+2] = v.z;
}

extern "C" void kernel_launch(void* const* d_in, const int* in_sizes, int n_in,
                              void* d_out, int out_size) {
    const float* inp    = (const float*)d_in[0];
    const float* coord  = (const float*)d_in[1];
    const float* cell   = (const float*)d_in[2];
    const float* enc_w  = (const float*)d_in[3];
    const float* enc_b  = (const float*)d_in[4];
    const float* body_w1= (const float*)d_in[5];
    const float* body_b1= (const float*)d_in[6];
    const float* body_w2= (const float*)d_in[7];
    const float* body_b2= (const float*)d_in[8];
    const float* rout_w = (const float*)d_in[9];
    const float* rout_b = (const float*)d_in[10];
    const float* off_w  = (const float*)d_in[11];
    const float* off_b  = (const float*)d_in[12];
    const float* tail_w = (const float*)d_in[13];
    const float* tail_b = (const float*)d_in[14];
    const float* wcmp   = (const float*)d_in[15];
    const float* wexp   = (const float*)d_in[16];
    float* out = (float*)d_out;

    k_enc_phase<<<513, 256>>>(inp, enc_w, enc_b,
                              body_w1, body_b1, body_w2, body_b2,
                              rout_w, rout_b, off_w, off_b);
    zero_pad<<<64, 512>>>();
    build_ab<<<32, 512>>>(wcmp, wexp);
    main_fused<<<2048, 128>>>();
    tail_conv<<<1024, 128>>>(tail_w, tail_b);
    gather_q<<<1024, 256>>>(coord, cell, out);
}

// round 8
// speedup vs baseline: 1.0003x; 1.0003x over previous
#include <cuda_runtime.h>
#include <cuda_bf16.h>

#define HLR 128
#define WLR 128
#define HH 512
#define WH 512
#define CC 64
#define NPIX (HH*WH)      // 262144
#define NPIX2 (514*512)   // padded plane: 1 zero row above + below
#define NQ 262144

typedef unsigned long long ull;

// ---- packed f32x2 helpers (sm_103a: fma.rn.f32x2 -> FFMA2) ----
__device__ __forceinline__ ull pk2(float lo, float hi) {
    ull r; asm("mov.b64 %0, {%1, %2};" : "=l"(r) : "f"(lo), "f"(hi)); return r;
}
__device__ __forceinline__ void upk2(ull v, float& lo, float& hi) {
    asm("mov.b64 {%0, %1}, %2;" : "=f"(lo), "=f"(hi) : "l"(v));
}
__device__ __forceinline__ ull fma2(ull a, ull b, ull c) {
    ull d; asm("fma.rn.f32x2 %0, %1, %2, %3;" : "=l"(d) : "l"(a), "l"(b), "l"(c)); return d;
}
__device__ __forceinline__ ull mul2(ull a, ull b) {
    ull d; asm("mul.rn.f32x2 %0, %1, %2;" : "=l"(d) : "l"(a), "l"(b)); return d;
}

// ---- scratch (device globals: allocation-free) ----
__device__ __align__(16) ull g_feat2[32*HLR*WLR];            // 4 MB [c2][pix]
// g_hidden2: channel-pair planes, PHASE-PERMUTED pixels, PADDED rows:
// [c2][(y+1)*512 + w*128 + g], x = 4*g + w; rows 0 and 513 are zero.
__device__ __align__(16) ull g_hidden2[32*NPIX2];            // ~67 MB
// g_pred4: PHASE-PERMUTED [y*512 + w*128 + g] {o0,o1,o2,-}
__device__ __align__(16) float4 g_pred4[NPIX];               // 4 MB
__device__ float g_off[16*2];
__device__ float g_r[16*4];
__device__ __align__(16) float g_A[16*512];      // [ph][c*8+k]
__device__ __align__(16) float g_B[16*512];      // [ph][k*64+c]

// ============ Kernel 1: encoder conv3x3 (blocks 0..511) + phase MLP (block 512) ============
__global__ void __launch_bounds__(256)
k_enc_phase(const float* __restrict__ inp,
            const float* __restrict__ ew, const float* __restrict__ eb,
            const float* __restrict__ w1, const float* __restrict__ b1,
            const float* __restrict__ w2, const float* __restrict__ b2,
            const float* __restrict__ rw, const float* __restrict__ rb,
            const float* __restrict__ ow, const float* __restrict__ ob) {
    __shared__ float sw[27*64];
    __shared__ float sb[64];
    __shared__ float sw2[64*65];
    __shared__ float se1[1024];
    __shared__ float se2[1024];
    int t = threadIdx.x;

    if (blockIdx.x < 512) {
        for (int idx = t; idx < 27*64; idx += 256) {
            int j = idx >> 6, c = idx & 63;
            sw[idx] = __ldg(&ew[c*27 + j]);
        }
        if (t < 64) sb[t] = __ldg(&eb[t]);
        __syncthreads();

        int px = blockIdx.x*32 + (t & 31);
        int grp = t >> 5;
        int x = px & 127, y = px >> 7;

        float in[27];
        #pragma unroll
        for (int ci = 0; ci < 3; ci++)
            #pragma unroll
            for (int ky = 0; ky < 3; ky++) {
                int yy = y + ky - 1;
                bool ry = ((unsigned)yy < 128u);
                #pragma unroll
                for (int kx = 0; kx < 3; kx++) {
                    int xx = x + kx - 1;
                    in[ci*9 + ky*3 + kx] = (ry && ((unsigned)xx < 128u))
                        ? __ldg(&inp[(ci*128 + yy)*128 + xx]) : 0.0f;
                }
            }
        #pragma unroll
        for (int u = 0; u < 2; u++) {
            int c4 = grp*2 + u;
            float4 acc = make_float4(sb[c4*4+0], sb[c4*4+1], sb[c4*4+2], sb[c4*4+3]);
            #pragma unroll
            for (int j = 0; j < 27; j++) {
                float fin = in[j];
                const float4 wv = *(const float4*)&sw[j*64 + c4*4];
                acc.x = fmaf(fin, wv.x, acc.x);
                acc.y = fmaf(fin, wv.y, acc.y);
                acc.z = fmaf(fin, wv.z, acc.z);
                acc.w = fmaf(fin, wv.w, acc.w);
            }
            g_feat2[(c4*2+0)*16384 + px] = pk2(acc.x, acc.y);
            g_feat2[(c4*2+1)*16384 + px] = pk2(acc.z, acc.w);
        }
    } else {
        for (int idx = t; idx < 4096; idx += 256) {
            int c = idx >> 6, j = idx & 63;
            sw2[c*65 + j] = __ldg(&w2[idx]);
        }
        #pragma unroll
        for (int it = 0; it < 4; it++) {
            int item = t + it*256;
            int ph = item >> 6, c = item & 63;
            int py = ph >> 2, px = ph & 3;
            float ch = (py + 0.5f)/4.0f; ch = ch - floorf(ch + 0.001f) - 0.5f;
            float cw = (px + 0.5f)/4.0f; cw = cw - floorf(cw + 0.001f) - 0.5f;
            const float cs = 0.25f;
            float s = __ldg(&b1[c]);
            s = fmaf(__ldg(&w1[c*4+0]), cs, s);
            s = fmaf(__ldg(&w1[c*4+1]), cs, s);
            s = fmaf(__ldg(&w1[c*4+2]), ch, s);
            s = fmaf(__ldg(&w1[c*4+3]), cw, s);
            se1[item] = fmaxf(s, 0.0f);
        }
        __syncthreads();
        #pragma unroll
        for (int it = 0; it < 4; it++) {
            int item = t + it*256;
            int ph = item >> 6, c = item & 63;
            float s = __ldg(&b2[c]);
            #pragma unroll 8
            for (int j = 0; j < 64; j++)
                s = fmaf(sw2[c*65 + j], se1[ph*64 + j], s);
            se2[item] = fmaxf(s, 0.0f);
        }
        __syncthreads();
        if (t < 96) {
            int ph = t / 6, which = t % 6;
            if (which < 2) {
                float s = __ldg(&ob[which]);
                for (int j = 0; j < 64; j++)
                    s = fmaf(__ldg(&ow[which*64 + j]), se2[ph*64 + j], s);
                g_off[ph*2 + which] = s;
            } else {
                int e = which - 2;
                float s = __ldg(&rb[e]);
                for (int j = 0; j < 64; j++)
                    s = fmaf(__ldg(&rw[e*64 + j]), se2[ph*64 + j], s);
                g_r[ph*4 + e] = 1.0f/(1.0f + expf(-s));
            }
        }
    }
}

// ============ Kernel 2: build A(r), B(r) (blocks 0..31) + zero pad rows (blocks 32..95) ============
__global__ void __launch_bounds__(512)
build_ab_pad(const float* __restrict__ wc, const float* __restrict__ we) {
    if (blockIdx.x < 32) {
        int t = blockIdx.x*512 + threadIdx.x;
        if (t < 8192) {
            int ph = t >> 9, rem = t & 511;
            int c = rem >> 3, k = rem & 7;
            float s = 0.0f;
            #pragma unroll
            for (int e = 0; e < 4; e++)
                s = fmaf(g_r[ph*4+e], __ldg(&we[(e*64 + c)*8 + k]), s);
            g_A[ph*512 + c*8 + k] = s;
        } else {
            int u = t - 8192;
            int ph = u >> 9, rem = u & 511;
            int k = rem >> 6, c = rem & 63;
            float s = 0.0f;
            #pragma unroll
            for (int e = 0; e < 4; e++)
                s = fmaf(g_r[ph*4+e], __ldg(&wc[(e*8 + k)*64 + c]), s);
            g_B[ph*512 + k*64 + c] = s;
        }
    } else {
        int t = (blockIdx.x - 32)*512 + threadIdx.x;   // 32768 items
        int c2 = t >> 10;
        int r  = (t >> 9) & 1;
        int i  = t & 511;
        g_hidden2[c2*NPIX2 + (r ? 513*512 : 0) + i] = 0ULL;
    }
}

// ============ Kernel 3: fused grid-sample + expert mixing (single pass, f2 cached) ============
__global__ void __launch_bounds__(128)
main_fused() {
    __shared__ ull sBt[4*264];   // [phl][c2*8+k] = (B[k][2c2], B[k][2c2+1])
    __shared__ ull sAt[4*264];   // [phl][c2*8+k] = (A[2c2][k], A[2c2+1][k])

    int tid = threadIdx.x;
    int p0 = blockIdx.x << 7;
    int y  = p0 >> 9;
    int X0 = p0 & 511;
    int py4 = y & 3;

    const ull* GB = (const ull*)g_B;
    for (int i = tid; i < 1024; i += 128) {
        int phl = i >> 8, ii = i & 255;
        int c2 = ii >> 3, k = ii & 7;
        int ph = py4*4 + phl;
        sBt[phl*264 + ii] = GB[ph*256 + k*32 + c2];
        sAt[phl*264 + ii] = pk2(g_A[ph*512 + (2*c2)*8 + k],
                                g_A[ph*512 + (2*c2+1)*8 + k]);
    }
    __syncthreads();

    int w    = tid >> 5;
    int lane = tid & 31;
    int x = X0 + 4*lane + w;
    int ph = py4*4 + w;

    float off0 = g_off[ph*2+0];
    float off1 = g_off[ph*2+1];

    float xs = ((float)x + 0.5f)*0.25f - 0.5f + off0;
    float ys = ((float)y + 0.5f)*0.25f - 0.5f + off1;
    float x0f = floorf(xs), y0f = floorf(ys);
    float wx1 = xs - x0f, wx0 = 1.0f - wx1;
    float wy1 = ys - y0f, wy0 = 1.0f - wy1;
    int x0 = (int)x0f, y0 = (int)y0f;
    int x1 = x0 + 1, y1 = y0 + 1;
    float mx0 = ((unsigned)x0 < 128u) ? 1.0f : 0.0f;
    float mx1 = ((unsigned)x1 < 128u) ? 1.0f : 0.0f;
    float my0 = ((unsigned)y0 < 128u) ? 1.0f : 0.0f;
    float my1 = ((unsigned)y1 < 128u) ? 1.0f : 0.0f;
    float w00 = wy0*wx0*my0*mx0;
    float w01 = wy0*wx1*my0*mx1;
    float w10 = wy1*wx0*my1*mx0;
    float w11 = wy1*wx1*my1*mx1;
    int xc0 = min(max(x0,0),127), xc1 = min(max(x1,0),127);
    int yc0 = min(max(y0,0),127), yc1 = min(max(y1,0),127);
    int i00 = yc0*128 + xc0, i01 = yc0*128 + xc1;
    int i10 = yc1*128 + xc0, i11 = yc1*128 + xc1;

    ull W00 = pk2(w00,w00), W01 = pk2(w01,w01);
    ull W10 = pk2(w10,w10), W11 = pk2(w11,w11);

    // ---- single pass: bilinear once (cached), mid = B * fea0 ----
    ull f2[32];
    ull acc[8] = {0,0,0,0,0,0,0,0};
    const ull* Bp = sBt + w*264;
    #pragma unroll
    for (int c2 = 0; c2 < 32; c2++) {
        const ull* fp = g_feat2 + c2*16384;
        ull f = fma2(__ldg(fp+i11), W11,
                fma2(__ldg(fp+i10), W10,
                fma2(__ldg(fp+i01), W01,
                mul2(__ldg(fp+i00), W00))));
        f2[c2] = f;
        #pragma unroll
        for (int k = 0; k < 8; k++)
            acc[k] = fma2(Bp[c2*8 + k], f, acc[k]);
    }
    ull mdup[8];
    #pragma unroll
    for (int k = 0; k < 8; k++) {
        float lo, hi; upk2(acc[k], lo, hi);
        float s = lo + hi;
        mdup[k] = pk2(s, s);
    }

    // ---- hidden = fea0 + A*mid, store permuted+padded ----
    int g = (X0 >> 2) + lane;
    ull* H = g_hidden2 + (((y+1) << 9) + (w << 7) + g);
    const ull* Ap = sAt + w*264;
    #pragma unroll
    for (int c2 = 0; c2 < 32; c2++) {
        ull h = f2[c2];
        #pragma unroll
        for (int k = 0; k < 8; k++)
            h = fma2(Ap[c2*8 + k], mdup[k], h);
        H[c2*NPIX2] = h;
    }
}

// ============ Kernel 4: tail conv3x3 (64 -> 3), streaming, pad rows, 2 rows/thread ============
__global__ void __launch_bounds__(128)
tail_conv(const float* __restrict__ tw, const float* __restrict__ tb) {
    __shared__ ull sw2[864];   // [c2][o][ky*3+kx] broadcast pairs

    for (int idx = threadIdx.x; idx < 864; idx += 128) {
        int c2 = idx / 27, rem = idx % 27;
        int o = rem / 9, t9 = rem % 9;
        sw2[idx] = pk2(__ldg(&tw[(o*64 + 2*c2)*9 + t9]),
                       __ldg(&tw[(o*64 + 2*c2+1)*9 + t9]));
    }
    __syncthreads();

    int w    = threadIdx.x >> 5;
    int lane = threadIdx.x & 31;
    int Y0 = (blockIdx.x >> 2) << 1;               // 256 row-pairs
    int g  = ((blockIdx.x & 3) << 5) + lane;       // 4 g-quarters

    int oC = (w << 7) + g;
    int oL, oR;
    bool vl = true, vr = true;
    if (w > 0) { oL = ((w-1) << 7) + g; }
    else       { oL = (3 << 7) + g - 1; vl = (g > 0); }
    if (w < 3) { oR = ((w+1) << 7) + g; }
    else       { oR = g + 1; vr = (g < 127); }

    const ull* pL = g_hidden2 + (ull)Y0*512 + oL;
    const ull* pC = g_hidden2 + (ull)Y0*512 + oC;
    const ull* pR = g_hidden2 + (ull)Y0*512 + oR;

    ull a0[3] = {0,0,0}, a1[3] = {0,0,0};

    #pragma unroll 4
    for (int c2 = 0; c2 < 32; c2++) {
        ull vL0 = vl ? __ldg(pL)        : 0ULL;
        ull vL1 = vl ? __ldg(pL + 512)  : 0ULL;
        ull vL2 = vl ? __ldg(pL + 1024) : 0ULL;
        ull vL3 = vl ? __ldg(pL + 1536) : 0ULL;
        ull vC0 = __ldg(pC);
        ull vC1 = __ldg(pC + 512);
        ull vC2 = __ldg(pC + 1024);
        ull vC3 = __ldg(pC + 1536);
        ull vR0 = vr ? __ldg(pR)        : 0ULL;
        ull vR1 = vr ? __ldg(pR + 512)  : 0ULL;
        ull vR2 = vr ? __ldg(pR + 1024) : 0ULL;
        ull vR3 = vr ? __ldg(pR + 1536) : 0ULL;
        pL += NPIX2; pC += NPIX2; pR += NPIX2;

        const ull* wp = &sw2[c2*27];
        #pragma unroll
        for (int o = 0; o < 3; o++) {
            ull w00 = wp[o*9+0], w01 = wp[o*9+1], w02 = wp[o*9+2];
            ull w10 = wp[o*9+3], w11 = wp[o*9+4], w12 = wp[o*9+5];
            ull w20 = wp[o*9+6], w21 = wp[o*9+7], w22 = wp[o*9+8];
            a0[o] = fma2(vL0,w00, fma2(vC0,w01, fma2(vR0,w02,
                    fma2(vL1,w10, fma2(vC1,w11, fma2(vR1,w12,
                    fma2(vL2,w20, fma2(vC2,w21, fma2(vR2,w22, a0[o])))))))));
            a1[o] = fma2(vL1,w00, fma2(vC1,w01, fma2(vR1,w02,
                    fma2(vL2,w10, fma2(vC2,w11, fma2(vR2,w12,
                    fma2(vL3,w20, fma2(vC3,w21, fma2(vR3,w22, a1[o])))))))));
        }
    }

    float b0 = __ldg(&tb[0]), b1 = __ldg(&tb[1]), b2 = __ldg(&tb[2]);
    {
        float l0,h0,l1,h1,l2,h2;
        upk2(a0[0], l0, h0); upk2(a0[1], l1, h1); upk2(a0[2], l2, h2);
        g_pred4[(Y0 << 9) + oC] = make_float4(b0+l0+h0, b1+l1+h1, b2+l2+h2, 0.0f);
        upk2(a1[0], l0, h0); upk2(a1[1], l1, h1); upk2(a1[2], l2, h2);
        g_pred4[((Y0+1) << 9) + oC] = make_float4(b0+l0+h0, b1+l1+h1, b2+l2+h2, 0.0f);
    }
}

// ============ Kernel 5: query gather (nearest, round-half-even) ============
__global__ void gather_q(const float* __restrict__ coord,
                         const float* __restrict__ cell,
                         float* __restrict__ out) {
    int q = blockIdx.x*blockDim.x + threadIdx.x;
    if (q >= NQ) return;
    float cy = __ldg(&coord[q*2+0]);
    float cx = __ldg(&coord[q*2+1]);
    float ly = __ldg(&cell[q*2+0]);
    float lx = __ldg(&cell[q*2+1]);
    float gyq = fminf(fmaxf(cy - ly*0.5f + 1e-6f, -1.0f + 1e-6f), 1.0f - 1e-6f);
    float gxq = fminf(fmaxf(cx - lx*0.5f + 1e-6f, -1.0f + 1e-6f), 1.0f - 1e-6f);
    int xi = (int)rintf((gxq + 1.0f)*0.5f*511.0f);
    int yi = (int)rintf((gyq + 1.0f)*0.5f*511.0f);
    xi = min(max(xi,0),511);
    yi = min(max(yi,0),511);
    int idx = (yi << 9) + ((xi & 3) << 7) + (xi >> 2);
    float4 v = __ldg(&g_pred4[idx]);
    out[q*3+0] = v.x;
    out[q*3+1] = v.y;
    out[q*3+2] = v.z;
}

extern "C" void kernel_launch(void* const* d_in, const int* in_sizes, int n_in,
                              void* d_out, int out_size) {
    const float* inp    = (const float*)d_in[0];
    const float* coord  = (const float*)d_in[1];
    const float* cell   = (const float*)d_in[2];
    const float* enc_w  = (const float*)d_in[3];
    const float* enc_b  = (const float*)d_in[4];
    const float* body_w1= (const float*)d_in[5];
    const float* body_b1= (const float*)d_in[6];
    const float* body_w2= (const float*)d_in[7];
    const float* body_b2= (const float*)d_in[8];
    const float* rout_w = (const float*)d_in[9];
    const float* rout_b = (const float*)d_in[10];
    const float* off_w  = (const float*)d_in[11];
    const float* off_b  = (const float*)d_in[12];
    const float* tail_w = (const float*)d_in[13];
    const float* tail_b = (const float*)d_in[14];
    const float* wcmp   = (const float*)d_in[15];
    const float* wexp   = (const float*)d_in[16];
    float* out = (float*)d_out;

    k_enc_phase<<<513, 256>>>(inp, enc_w, enc_b,
                              body_w1, body_b1, body_w2, body_b2,
                              rout_w, rout_b, off_w, off_b);
    build_ab_pad<<<96, 512>>>(wcmp, wexp);
    main_fused<<<2048, 128>>>();
    tail_conv<<<1024, 128>>>(tail_w, tail_b);
    gather_q<<<1024, 256>>>(coord, cell, out);
}

// round 9
// speedup vs baseline: 1.3918x; 1.3913x over previous
#include <cuda_runtime.h>
#include <cuda_bf16.h>

#define HLR 128
#define WLR 128
#define HH 512
#define WH 512
#define NPIX (HH*WH)      // 262144
#define NPIX2 (514*512)   // padded plane rows 0..513
#define NQ 262144

typedef unsigned long long ull;

// ---- packed f32x2 helpers (sm_103a: fma.rn.f32x2 -> FFMA2) ----
__device__ __forceinline__ ull pk2(float lo, float hi) {
    ull r; asm("mov.b64 %0, {%1, %2};" : "=l"(r) : "f"(lo), "f"(hi)); return r;
}
__device__ __forceinline__ void upk2(ull v, float& lo, float& hi) {
    asm("mov.b64 {%0, %1}, %2;" : "=f"(lo), "=f"(hi) : "l"(v));
}
__device__ __forceinline__ ull fma2(ull a, ull b, ull c) {
    ull d; asm("fma.rn.f32x2 %0, %1, %2, %3;" : "=l"(d) : "l"(a), "l"(b), "l"(c)); return d;
}
__device__ __forceinline__ ull mul2(ull a, ull b) {
    ull d; asm("mul.rn.f32x2 %0, %1, %2;" : "=l"(d) : "l"(a), "l"(b)); return d;
}

// ---- scratch (device globals: allocation-free) ----
__device__ __align__(16) ull g_feat2[32*HLR*WLR];   // 4 MB LR feat channel pairs [c2][pix]
__device__ __align__(16) ull g_mid2[4*NPIX2];       // 8.4 MB mid k-pairs, permuted+padded
__device__ __align__(16) float4 g_G4[9*HLR*WLR];    // 2.3 MB G planes [tap][LRpix]{o0,o1,o2,-}
__device__ __align__(16) ull g_T2[3*9*16*4];        // T k-pairs [o][tap][ph][k2]
__device__ __align__(16) float4 g_pred4[NPIX];      // 4 MB, phase-permuted
__device__ float g_off[16*2];
__device__ float g_r[16*4];
__device__ __align__(16) float g_B[16*512];         // [ph][k*64+c]

// ============ Kernel 1: encoder conv3x3 (blocks 0..511) + phase MLP (block 512) ============
__global__ void __launch_bounds__(256)
k_enc_phase(const float* __restrict__ inp,
            const float* __restrict__ ew, const float* __restrict__ eb,
            const float* __restrict__ w1, const float* __restrict__ b1,
            const float* __restrict__ w2, const float* __restrict__ b2,
            const float* __restrict__ rw, const float* __restrict__ rb,
            const float* __restrict__ ow, const float* __restrict__ ob) {
    __shared__ float sw[27*64];
    __shared__ float sb[64];
    __shared__ float sw2[64*65];
    __shared__ float se1[1024];
    __shared__ float se2[1024];
    int t = threadIdx.x;

    if (blockIdx.x < 512) {
        for (int idx = t; idx < 27*64; idx += 256) {
            int j = idx >> 6, c = idx & 63;
            sw[idx] = __ldg(&ew[c*27 + j]);
        }
        if (t < 64) sb[t] = __ldg(&eb[t]);
        __syncthreads();

        int px = blockIdx.x*32 + (t & 31);
        int grp = t >> 5;
        int x = px & 127, y = px >> 7;

        float in[27];
        #pragma unroll
        for (int ci = 0; ci < 3; ci++)
            #pragma unroll
            for (int ky = 0; ky < 3; ky++) {
                int yy = y + ky - 1;
                bool ry = ((unsigned)yy < 128u);
                #pragma unroll
                for (int kx = 0; kx < 3; kx++) {
                    int xx = x + kx - 1;
                    in[ci*9 + ky*3 + kx] = (ry && ((unsigned)xx < 128u))
                        ? __ldg(&inp[(ci*128 + yy)*128 + xx]) : 0.0f;
                }
            }
        #pragma unroll
        for (int u = 0; u < 2; u++) {
            int c4 = grp*2 + u;
            float4 acc = make_float4(sb[c4*4+0], sb[c4*4+1], sb[c4*4+2], sb[c4*4+3]);
            #pragma unroll
            for (int j = 0; j < 27; j++) {
                float fin = in[j];
                const float4 wv = *(const float4*)&sw[j*64 + c4*4];
                acc.x = fmaf(fin, wv.x, acc.x);
                acc.y = fmaf(fin, wv.y, acc.y);
                acc.z = fmaf(fin, wv.z, acc.z);
                acc.w = fmaf(fin, wv.w, acc.w);
            }
            g_feat2[(c4*2+0)*16384 + px] = pk2(acc.x, acc.y);
            g_feat2[(c4*2+1)*16384 + px] = pk2(acc.z, acc.w);
        }
    } else {
        for (int idx = t; idx < 4096; idx += 256) {
            int c = idx >> 6, j = idx & 63;
            sw2[c*65 + j] = __ldg(&w2[idx]);
        }
        #pragma unroll
        for (int it = 0; it < 4; it++) {
            int item = t + it*256;
            int ph = item >> 6, c = item & 63;
            int py = ph >> 2, px = ph & 3;
            float ch = (py + 0.5f)/4.0f; ch = ch - floorf(ch + 0.001f) - 0.5f;
            float cw = (px + 0.5f)/4.0f; cw = cw - floorf(cw + 0.001f) - 0.5f;
            const float cs = 0.25f;
            float s = __ldg(&b1[c]);
            s = fmaf(__ldg(&w1[c*4+0]), cs, s);
            s = fmaf(__ldg(&w1[c*4+1]), cs, s);
            s = fmaf(__ldg(&w1[c*4+2]), ch, s);
            s = fmaf(__ldg(&w1[c*4+3]), cw, s);
            se1[item] = fmaxf(s, 0.0f);
        }
        __syncthreads();
        #pragma unroll
        for (int it = 0; it < 4; it++) {
            int item = t + it*256;
            int ph = item >> 6, c = item & 63;
            float s = __ldg(&b2[c]);
            #pragma unroll 8
            for (int j = 0; j < 64; j++)
                s = fmaf(sw2[c*65 + j], se1[ph*64 + j], s);
            se2[item] = fmaxf(s, 0.0f);
        }
        __syncthreads();
        if (t < 96) {
            int ph = t / 6, which = t % 6;
            if (which < 2) {
                float s = __ldg(&ob[which]);
                for (int j = 0; j < 64; j++)
                    s = fmaf(__ldg(&ow[which*64 + j]), se2[ph*64 + j], s);
                g_off[ph*2 + which] = s;
            } else {
                int e = which - 2;
                float s = __ldg(&rb[e]);
                for (int j = 0; j < 64; j++)
                    s = fmaf(__ldg(&rw[e*64 + j]), se2[ph*64 + j], s);
                g_r[ph*4 + e] = 1.0f/(1.0f + expf(-s));
            }
        }
    }
}

// ============ Kernel 2: prep — B (blk 0..15), mid pads (16..23), T (24..27), G4 (28..59) ============
__global__ void __launch_bounds__(512)
prep_kernel(const float* __restrict__ wc, const float* __restrict__ we,
            const float* __restrict__ tw) {
    __shared__ ull w2g[864];   // only used by G4 branch
    int b = blockIdx.x, tid = threadIdx.x;

    if (b < 16) {
        int u = b*512 + tid;                 // 8192 B entries
        int ph = u >> 9, rem = u & 511;
        int k = rem >> 6, c = rem & 63;
        float s = 0.0f;
        #pragma unroll
        for (int e = 0; e < 4; e++)
            s = fmaf(g_r[ph*4+e], __ldg(&wc[(e*8 + k)*64 + c]), s);
        g_B[ph*512 + k*64 + c] = s;
    } else if (b < 24) {
        int it = (b-16)*512 + tid;           // 4096 pad items
        int k2 = it >> 10, r = (it >> 9) & 1, i = it & 511;
        g_mid2[k2*NPIX2 + (r ? 513*512 : 0) + i] = 0ULL;
    } else if (b < 28) {
        int u = (b-24)*512 + tid;            // 1728 T entries
        if (u < 1728) {
            int k2 = u & 3, ph = (u >> 2) & 15, t9 = (u >> 6) % 9, o = u / 576;
            float s0 = 0.0f, s1 = 0.0f;
            #pragma unroll
            for (int e = 0; e < 4; e++) {
                float re = g_r[ph*4 + e];
                float a0 = 0.0f, a1 = 0.0f;
                for (int c = 0; c < 64; c++) {
                    float twv = __ldg(&tw[(o*64 + c)*9 + t9]);
                    a0 = fmaf(twv, __ldg(&we[(e*64 + c)*8 + 2*k2]),   a0);
                    a1 = fmaf(twv, __ldg(&we[(e*64 + c)*8 + 2*k2+1]), a1);
                }
                s0 = fmaf(re, a0, s0);
                s1 = fmaf(re, a1, s1);
            }
            g_T2[((o*9 + t9)*16 + ph)*4 + k2] = pk2(s0, s1);
        }
    } else {
        // G4 build: G[o][tap] = sum_c tw[o][c][tap] * feat[c], 512 px/block
        for (int idx = tid; idx < 864; idx += 512) {
            int c2 = idx / 27, r = idx % 27, t9 = r / 3, o = r % 3;
            w2g[idx] = pk2(__ldg(&tw[(o*64 + 2*c2)*9 + t9]),
                           __ldg(&tw[(o*64 + 2*c2 + 1)*9 + t9]));
        }
        __syncthreads();
        int pix = (b - 28)*512 + tid;
        ull a[27];
        #pragma unroll
        for (int j = 0; j < 27; j++) a[j] = 0ULL;
        for (int c2 = 0; c2 < 32; c2++) {
            ull f = g_feat2[c2*16384 + pix];
            #pragma unroll
            for (int j = 0; j < 27; j++)
                a[j] = fma2(f, w2g[c2*27 + j], a[j]);
        }
        #pragma unroll
        for (int t9 = 0; t9 < 9; t9++) {
            float l, h;
            float4 v;
            upk2(a[t9*3+0], l, h); v.x = l + h;
            upk2(a[t9*3+1], l, h); v.y = l + h;
            upk2(a[t9*3+2], l, h); v.z = l + h;
            v.w = 0.0f;
            g_G4[t9*16384 + pix] = v;
        }
    }
}

// ============ Kernel 3: fused grid-sample + mid = B*fea0 (stores only mid) ============
__global__ void __launch_bounds__(128)
main_fused() {
    __shared__ ull sBt[4*264];   // [phl][c2*8+k] = (B[k][2c2], B[k][2c2+1])

    int tid = threadIdx.x;
    int p0 = blockIdx.x << 7;
    int y  = p0 >> 9;
    int X0 = p0 & 511;
    int py4 = y & 3;

    const ull* GB = (const ull*)g_B;
    for (int i = tid; i < 1024; i += 128) {
        int phl = i >> 8, ii = i & 255;
        int c2 = ii >> 3, k = ii & 7;
        int ph = py4*4 + phl;
        sBt[phl*264 + ii] = GB[ph*256 + k*32 + c2];
    }
    __syncthreads();

    int w    = tid >> 5;
    int lane = tid & 31;
    int x = X0 + 4*lane + w;
    int ph = py4*4 + w;

    float off0 = g_off[ph*2+0];
    float off1 = g_off[ph*2+1];

    float xs = ((float)x + 0.5f)*0.25f - 0.5f + off0;
    float ys = ((float)y + 0.5f)*0.25f - 0.5f + off1;
    float x0f = floorf(xs), y0f = floorf(ys);
    float wx1 = xs - x0f, wx0 = 1.0f - wx1;
    float wy1 = ys - y0f, wy0 = 1.0f - wy1;
    int x0 = (int)x0f, y0 = (int)y0f;
    int x1 = x0 + 1, y1 = y0 + 1;
    float mx0 = ((unsigned)x0 < 128u) ? 1.0f : 0.0f;
    float mx1 = ((unsigned)x1 < 128u) ? 1.0f : 0.0f;
    float my0 = ((unsigned)y0 < 128u) ? 1.0f : 0.0f;
    float my1 = ((unsigned)y1 < 128u) ? 1.0f : 0.0f;
    float w00 = wy0*wx0*my0*mx0;
    float w01 = wy0*wx1*my0*mx1;
    float w10 = wy1*wx0*my1*mx0;
    float w11 = wy1*wx1*my1*mx1;
    int xc0 = min(max(x0,0),127), xc1 = min(max(x1,0),127);
    int yc0 = min(max(y0,0),127), yc1 = min(max(y1,0),127);
    int i00 = yc0*128 + xc0, i01 = yc0*128 + xc1;
    int i10 = yc1*128 + xc0, i11 = yc1*128 + xc1;

    ull W00 = pk2(w00,w00), W01 = pk2(w01,w01);
    ull W10 = pk2(w10,w10), W11 = pk2(w11,w11);

    ull acc[8] = {0,0,0,0,0,0,0,0};
    const ull* Bp = sBt + w*264;
    #pragma unroll
    for (int c2 = 0; c2 < 32; c2++) {
        const ull* fp = g_feat2 + c2*16384;
        ull f = fma2(__ldg(fp+i11), W11,
                fma2(__ldg(fp+i10), W10,
                fma2(__ldg(fp+i01), W01,
                mul2(__ldg(fp+i00), W00))));
        #pragma unroll
        for (int k = 0; k < 8; k++)
            acc[k] = fma2(Bp[c2*8 + k], f, acc[k]);
    }
    float m[8];
    #pragma unroll
    for (int k = 0; k < 8; k++) {
        float lo, hi; upk2(acc[k], lo, hi);
        m[k] = lo + hi;
    }

    int g = (X0 >> 2) + lane;
    int moff = ((y+1) << 9) + (w << 7) + g;
    #pragma unroll
    for (int k2 = 0; k2 < 4; k2++)
        g_mid2[k2*NPIX2 + moff] = pk2(m[2*k2], m[2*k2+1]);
}

// ============ Kernel 4: tail conv via G-planes + T*mid (no 64-ch hidden) ============
__global__ void __launch_bounds__(128)
tail_conv(const float* __restrict__ tb) {
    __shared__ ull sT[432];              // [(t*4+pxp)*12 + o*4 + k2]
    __shared__ float s_off0[16], s_off1[16];

    int tid = threadIdx.x;
    int p0 = blockIdx.x << 7;
    int y  = p0 >> 9;
    int X0 = p0 & 511;
    int py4 = y & 3;

    for (int idx = tid; idx < 432; idx += 128) {
        int t9 = idx / 48, rem = idx % 48;
        int pxp = rem / 12, j = rem % 12;
        int o = j >> 2, k2 = j & 3;
        int dy = t9 / 3 - 1;
        int pyp = (py4 + dy + 4) & 3;
        int ph = pyp*4 + pxp;
        sT[idx] = g_T2[((o*9 + t9)*16 + ph)*4 + k2];
    }
    if (tid < 16) {
        s_off0[tid] = g_off[tid*2+0];
        s_off1[tid] = g_off[tid*2+1];
    }
    __syncthreads();

    int w    = tid >> 5;
    int lane = tid & 31;
    int x = X0 + 4*lane + w;
    int g = (X0 >> 2) + lane;

    float po0 = 0.0f, po1 = 0.0f, po2 = 0.0f;
    ull a2[3] = {0ULL, 0ULL, 0ULL};

    #pragma unroll
    for (int t9 = 0; t9 < 9; t9++) {
        const int dy = t9/3 - 1;
        const int dx = t9%3 - 1;
        int wd  = w + dx;
        int pxp = wd & 3;
        int pyp = (py4 + dy + 4) & 3;
        int ph  = pyp*4 + pxp;
        float off0 = s_off0[ph], off1 = s_off1[ph];
        float tm = (((unsigned)(x+dx) < 512u) && ((unsigned)(y+dy) < 512u)) ? 1.0f : 0.0f;

        float xs = ((float)(x+dx) + 0.5f)*0.25f - 0.5f + off0;
        float ys = ((float)(y+dy) + 0.5f)*0.25f - 0.5f + off1;
        float x0f = floorf(xs), y0f = floorf(ys);
        float wx1 = xs - x0f, wx0 = 1.0f - wx1;
        float wy1 = ys - y0f, wy0 = 1.0f - wy1;
        int x0 = (int)x0f, y0i = (int)y0f;
        int x1 = x0 + 1, y1i = y0i + 1;
        float wx0m = ((unsigned)x0 < 128u) ? wx0 : 0.0f;
        float wx1m = ((unsigned)x1 < 128u) ? wx1 : 0.0f;
        float wy0m = (((unsigned)y0i < 128u) ? wy0 : 0.0f) * tm;
        float wy1m = (((unsigned)y1i < 128u) ? wy1 : 0.0f) * tm;
        float w00 = wy0m*wx0m, w01 = wy0m*wx1m;
        float w10 = wy1m*wx0m, w11 = wy1m*wx1m;
        int xc0 = min(max(x0,0),127),  xc1 = min(max(x1,0),127);
        int yc0 = min(max(y0i,0),127), yc1 = min(max(y1i,0),127);

        const float4* Gp = g_G4 + t9*16384;
        float4 v00 = __ldg(Gp + yc0*128 + xc0);
        float4 v01 = __ldg(Gp + yc0*128 + xc1);
        float4 v10 = __ldg(Gp + yc1*128 + xc0);
        float4 v11 = __ldg(Gp + yc1*128 + xc1);
        po0 = fmaf(w00,v00.x, fmaf(w01,v01.x, fmaf(w10,v10.x, fmaf(w11,v11.x, po0))));
        po1 = fmaf(w00,v00.y, fmaf(w01,v01.y, fmaf(w10,v10.y, fmaf(w11,v11.y, po1))));
        po2 = fmaf(w00,v00.z, fmaf(w01,v01.z, fmaf(w10,v10.z, fmaf(w11,v11.z, po2))));

        int gq = min(max(g + (wd >> 2), 0), 127);
        int moff = ((y + 1 + dy) << 9) + (pxp << 7) + gq;
        ull mm = pk2(tm, tm);
        ull m0 = mul2(__ldg(g_mid2 + 0*NPIX2 + moff), mm);
        ull m1 = mul2(__ldg(g_mid2 + 1*NPIX2 + moff), mm);
        ull m2 = mul2(__ldg(g_mid2 + 2*NPIX2 + moff), mm);
        ull m3 = mul2(__ldg(g_mid2 + 3*NPIX2 + moff), mm);
        const ull* Tp = sT + (t9*4 + pxp)*12;
        a2[0] = fma2(Tp[0],m0, fma2(Tp[1],m1, fma2(Tp[2], m2, fma2(Tp[3], m3, a2[0]))));
        a2[1] = fma2(Tp[4],m0, fma2(Tp[5],m1, fma2(Tp[6], m2, fma2(Tp[7], m3, a2[1]))));
        a2[2] = fma2(Tp[8],m0, fma2(Tp[9],m1, fma2(Tp[10],m2, fma2(Tp[11],m3, a2[2]))));
    }

    float l, h;
    upk2(a2[0], l, h); po0 += l + h;
    upk2(a2[1], l, h); po1 += l + h;
    upk2(a2[2], l, h); po2 += l + h;
    g_pred4[(y << 9) + (w << 7) + g] =
        make_float4(po0 + __ldg(&tb[0]), po1 + __ldg(&tb[1]), po2 + __ldg(&tb[2]), 0.0f);
}

// ============ Kernel 5: query gather (nearest, round-half-even) ============
__global__ void gather_q(const float* __restrict__ coord,
                         const float* __restrict__ cell,
                         float* __restrict__ out) {
    int q = blockIdx.x*blockDim.x + threadIdx.x;
    if (q >= NQ) return;
    float cy = __ldg(&coord[q*2+0]);
    float cx = __ldg(&coord[q*2+1]);
    float ly = __ldg(&cell[q*2+0]);
    float lx = __ldg(&cell[q*2+1]);
    float gyq = fminf(fmaxf(cy - ly*0.5f + 1e-6f, -1.0f + 1e-6f), 1.0f - 1e-6f);
    float gxq = fminf(fmaxf(cx - lx*0.5f + 1e-6f, -1.0f + 1e-6f), 1.0f - 1e-6f);
    int xi = (int)rintf((gxq + 1.0f)*0.5f*511.0f);
    int yi = (int)rintf((gyq + 1.0f)*0.5f*511.0f);
    xi = min(max(xi,0),511);
    yi = min(max(yi,0),511);
    int idx = (yi << 9) + ((xi & 3) << 7) + (xi >> 2);
    float4 v = __ldg(&g_pred4[idx]);
    out[q*3+0] = v.x;
    out[q*3+1] = v.y;
    out[q*3+2] = v.z;
}

extern "C" void kernel_launch(void* const* d_in, const int* in_sizes, int n_in,
                              void* d_out, int out_size) {
    const float* inp    = (const float*)d_in[0];
    const float* coord  = (const float*)d_in[1];
    const float* cell   = (const float*)d_in[2];
    const float* enc_w  = (const float*)d_in[3];
    const float* enc_b  = (const float*)d_in[4];
    const float* body_w1= (const float*)d_in[5];
    const float* body_b1= (const float*)d_in[6];
    const float* body_w2= (const float*)d_in[7];
    const float* body_b2= (const float*)d_in[8];
    const float* rout_w = (const float*)d_in[9];
    const float* rout_b = (const float*)d_in[10];
    const float* off_w  = (const float*)d_in[11];
    const float* off_b  = (const float*)d_in[12];
    const float* tail_w = (const float*)d_in[13];
    const float* tail_b = (const float*)d_in[14];
    const float* wcmp   = (const float*)d_in[15];
    const float* wexp   = (const float*)d_in[16];
    float* out = (float*)d_out;

    k_enc_phase<<<513, 256>>>(inp, enc_w, enc_b,
                              body_w1, body_b1, body_w2, body_b2,
                              rout_w, rout_b, off_w, off_b);
    prep_kernel<<<60, 512>>>(wcmp, wexp, tail_w);
    main_fused<<<2048, 128>>>();
    tail_conv<<<2048, 128>>>(tail_b);
    gather_q<<<1024, 256>>>(coord, cell, out);
}